// round 5
// baseline (speedup 1.0000x reference)
#include <cuda_runtime.h>

#define BETA 0.99f
#define TH   1.0f
#define NSTEPS 25
#define N1   100
#define N2   10
#define KIN  21
#define BDIM 64

__global__ __launch_bounds__(BDIM)
void snn_kernel(const float* __restrict__ x,    // [B,21]
                const float* __restrict__ W1,   // [100,21]
                const float* __restrict__ b1,   // [100]
                const float* __restrict__ W2,   // [10,100]
                const float* __restrict__ b2,   // [10]
                float* __restrict__ out,        // [2,25,B,10]
                int B)
{
    __shared__ float sW1[N1][KIN];
    __shared__ float sW2T[N1][12];   // W2 transposed, padded to 12 floats
    __shared__ float sb1[N1];
    __shared__ float sb2[N2];
    __shared__ float sc[N1][BDIM];   // step-invariant cur1 per element

    const int tid = threadIdx.x;

    for (int i = tid; i < N1 * KIN; i += BDIM) sW1[i / KIN][i % KIN] = W1[i];
    for (int i = tid; i < N2 * N1; i += BDIM) {
        int k = i / N1, j = i % N1;
        sW2T[j][k] = W2[i];
    }
    for (int i = tid; i < N1; i += BDIM) sb1[i] = b1[i];
    if (tid < N2) sb2[tid] = b2[tid];
    __syncthreads();

    const int e = blockIdx.x * BDIM + tid;
    if (e >= B) return;

    // ---- load x ----
    float xv[KIN];
#pragma unroll
    for (int k = 0; k < KIN; k++) xv[k] = x[e * KIN + k];

    // ---- cur1: ascending-k fma chain from 0, then + b1 (separately rounded) ----
#pragma unroll 4
    for (int j = 0; j < N1; j++) {
        float a = 0.0f;
#pragma unroll
        for (int k = 0; k < KIN; k++) a = fmaf(xv[k], sW1[j][k], a);
        sc[j][tid] = __fadd_rn(a, sb1[j]);
    }

    float mem[N1];
#pragma unroll
    for (int j = 0; j < N1; j++) mem[j] = 0.0f;

    float mem2[N2];
#pragma unroll
    for (int k = 0; k < N2; k++) mem2[k] = 0.0f;

    float* __restrict__ spkout = out;
    float* __restrict__ memout = out + (size_t)NSTEPS * B * N2;

    for (int t = 0; t < NSTEPS; t++) {
        float acc[N2];
#pragma unroll
        for (int k = 0; k < N2; k++) acc[k] = 0.0f;

        // ---- layer 1: XLA-GPU rounding order: fma(beta, mem, cur) then -reset ----
#pragma unroll
        for (int j = 0; j < N1; j++) {
            float mprev = mem[j];
            float r = (mprev > TH) ? 1.0f : 0.0f;    // reset == prev-step spike
            float m = __fsub_rn(fmaf(BETA, mprev, sc[j][tid]), r);
            mem[j] = m;
            float s = (m > TH) ? 1.0f : 0.0f;        // spike (exactly 0/1)

            const float4 w0  = *(const float4*)&sW2T[j][0];
            const float4 w1  = *(const float4*)&sW2T[j][4];
            const float2 w2v = *(const float2*)&sW2T[j][8];
            acc[0] = fmaf(s, w0.x, acc[0]);
            acc[1] = fmaf(s, w0.y, acc[1]);
            acc[2] = fmaf(s, w0.z, acc[2]);
            acc[3] = fmaf(s, w0.w, acc[3]);
            acc[4] = fmaf(s, w1.x, acc[4]);
            acc[5] = fmaf(s, w1.y, acc[5]);
            acc[6] = fmaf(s, w1.z, acc[6]);
            acc[7] = fmaf(s, w1.w, acc[7]);
            acc[8] = fmaf(s, w2v.x, acc[8]);
            acc[9] = fmaf(s, w2v.y, acc[9]);
        }

        // ---- layer 2: same contraction pattern ----
        const size_t obase = ((size_t)t * B + e) * N2;
        float so[N2], mo[N2];
#pragma unroll
        for (int k = 0; k < N2; k++) {
            float cc = __fadd_rn(acc[k], sb2[k]);    // bias after full sum
            float mprev = mem2[k];
            float r = (mprev > TH) ? 1.0f : 0.0f;
            float m = __fsub_rn(fmaf(BETA, mprev, cc), r);
            mem2[k] = m;
            so[k] = (m > TH) ? 1.0f : 0.0f;
            mo[k] = m;
        }
#pragma unroll
        for (int k = 0; k < N2; k += 2) {
            *(float2*)&spkout[obase + k] = make_float2(so[k], so[k + 1]);
            *(float2*)&memout[obase + k] = make_float2(mo[k], mo[k + 1]);
        }
    }
}

extern "C" void kernel_launch(void* const* d_in, const int* in_sizes, int n_in,
                              void* d_out, int out_size)
{
    const float* x  = (const float*)d_in[0];
    const float* W1 = (const float*)d_in[1];
    const float* b1 = (const float*)d_in[2];
    const float* W2 = (const float*)d_in[3];
    const float* b2 = (const float*)d_in[4];
    float* out = (float*)d_out;

    const int B = in_sizes[0] / KIN;
    const int grid = (B + BDIM - 1) / BDIM;
    snn_kernel<<<grid, BDIM>>>(x, W1, b1, W2, b2, out, B);
}

// round 7
// speedup vs baseline: 5.5107x; 5.5107x over previous
#include <cuda_runtime.h>

#define BETA 0.99f
#define TH   1.0f
#define NSTEPS 25
#define N1   100
#define N2   10
#define KIN  21
#define BDIM 64

// packed f32x2 FMA (sm_103a): two independent rn-FMAs in one instruction
#define FMA_F32X2(d, a, b, c) \
    asm("fma.rn.f32x2 %0, %1, %2, %3;" : "=l"(d) : "l"(a), "l"(b), "l"(c))
#define PACK_SS(d, s) \
    asm("mov.b64 %0, {%1, %1};" : "=l"(d) : "f"(s))
#define UNPACK_F32X2(lo, hi, v) \
    asm("mov.b64 {%0, %1}, %2;" : "=f"(lo), "=f"(hi) : "l"(v))

__global__ __launch_bounds__(BDIM)
void snn_kernel(const float* __restrict__ x,    // [B,21]
                const float* __restrict__ W1,   // [100,21]
                const float* __restrict__ b1,   // [100]
                const float* __restrict__ W2,   // [10,100]
                const float* __restrict__ b2,   // [10]
                float* __restrict__ out,        // [2,25,B,10]
                int B)
{
    __shared__ float sW1[N1][KIN];
    __shared__ unsigned long long sW2p[N1][5];  // W2^T row j as 5 packed f32x2
    __shared__ float sb1[N1];
    __shared__ float sb2[N2];
    __shared__ float sc[N1][BDIM];              // step-invariant cur1 per element

    const int tid = threadIdx.x;

    for (int i = tid; i < N1 * KIN; i += BDIM) sW1[i / KIN][i % KIN] = W1[i];
    for (int i = tid; i < N1 * 5; i += BDIM) {
        int j = i / 5, k2 = i % 5;
        float lo = W2[(2 * k2) * N1 + j];
        float hi = W2[(2 * k2 + 1) * N1 + j];
        unsigned long long p;
        asm("mov.b64 %0, {%1, %2};" : "=l"(p) : "f"(lo), "f"(hi));
        sW2p[j][k2] = p;
    }
    for (int i = tid; i < N1; i += BDIM) sb1[i] = b1[i];
    if (tid < N2) sb2[tid] = b2[tid];
    __syncthreads();

    const int e = blockIdx.x * BDIM + tid;
    if (e >= B) return;

    // ---- prologue: cur1 = ascending-k fma chain from 0, then +b1 (scoped so xv dies) ----
    {
        float xv[KIN];
#pragma unroll
        for (int k = 0; k < KIN; k++) xv[k] = x[e * KIN + k];
#pragma unroll 4
        for (int j = 0; j < N1; j++) {
            float a = 0.0f;
#pragma unroll
            for (int k = 0; k < KIN; k++) a = fmaf(xv[k], sW1[j][k], a);
            sc[j][tid] = __fadd_rn(a, sb1[j]);
        }
    }

    float mem[N1];
#pragma unroll
    for (int j = 0; j < N1; j++) mem[j] = 0.0f;

    float mem2[N2];
#pragma unroll
    for (int k = 0; k < N2; k++) mem2[k] = 0.0f;

    float* __restrict__ spkout = out;
    float* __restrict__ memout = out + (size_t)NSTEPS * B * N2;

    for (int t = 0; t < NSTEPS; t++) {
        unsigned long long acc2[5];
#pragma unroll
        for (int k = 0; k < 5; k++) acc2[k] = 0ull;

        // ---- layer 1: membrane update (XLA order) + packed spike-gated fc2 chains ----
#pragma unroll 5
        for (int j = 0; j < N1; j++) {
            float mprev = mem[j];
            float r = (mprev > TH) ? 1.0f : 0.0f;           // reset == prev spike
            float m = __fsub_rn(fmaf(BETA, mprev, sc[j][tid]), r);
            mem[j] = m;
            float s = (m > TH) ? 1.0f : 0.0f;               // spike, exactly 0/1

            unsigned long long ss;
            PACK_SS(ss, s);
#pragma unroll
            for (int k = 0; k < 5; k++) {
                unsigned long long w = sW2p[j][k];
                FMA_F32X2(acc2[k], ss, w, acc2[k]);         // per-component rn FMA, same order
            }
        }

        // ---- layer 2 (scalar, 10 neurons) ----
        const size_t obase = ((size_t)t * B + e) * N2;
        float so[N2], mo[N2];
#pragma unroll
        for (int k = 0; k < 5; k++) {
            float a0, a1;
            UNPACK_F32X2(a0, a1, acc2[k]);
#pragma unroll
            for (int q = 0; q < 2; q++) {
                int kk = 2 * k + q;
                float av = q ? a1 : a0;
                float cc = __fadd_rn(av, sb2[kk]);          // bias after full sum
                float mprev = mem2[kk];
                float r = (mprev > TH) ? 1.0f : 0.0f;
                float m = __fsub_rn(fmaf(BETA, mprev, cc), r);
                mem2[kk] = m;
                so[kk] = (m > TH) ? 1.0f : 0.0f;
                mo[kk] = m;
            }
        }
#pragma unroll
        for (int k = 0; k < N2; k += 2) {
            *(float2*)&spkout[obase + k] = make_float2(so[k], so[k + 1]);
            *(float2*)&memout[obase + k] = make_float2(mo[k], mo[k + 1]);
        }
    }
}

extern "C" void kernel_launch(void* const* d_in, const int* in_sizes, int n_in,
                              void* d_out, int out_size)
{
    const float* x  = (const float*)d_in[0];
    const float* W1 = (const float*)d_in[1];
    const float* b1 = (const float*)d_in[2];
    const float* W2 = (const float*)d_in[3];
    const float* b2 = (const float*)d_in[4];
    float* out = (float*)d_out;

    const int B = in_sizes[0] / KIN;
    const int grid = (B + BDIM - 1) / BDIM;
    snn_kernel<<<grid, BDIM>>>(x, W1, b1, W2, b2, out, B);
}

// round 12
// speedup vs baseline: 6.3061x; 1.1443x over previous
#include <cuda_runtime.h>

#define BETA 0.99f
#define TH   1.0f
#define NSTEPS 25
#define N1   100
#define N2   10
#define KIN  21
#define BDIM 64

// packed f32x2 FMA (sm_103a): two independent rn-FMAs in one instruction
#define FMA_F32X2(d, a, b, c) \
    asm("fma.rn.f32x2 %0, %1, %2, %3;" : "=l"(d) : "l"(a), "l"(b), "l"(c))
#define PACK_SS(d, s) \
    asm("mov.b64 %0, {%1, %1};" : "=l"(d) : "f"(s))
#define UNPACK_F32X2(lo, hi, v) \
    asm("mov.b64 {%0, %1}, %2;" : "=f"(lo), "=f"(hi) : "l"(v))

__global__ __launch_bounds__(BDIM, 7)
void snn_kernel(const float* __restrict__ x,    // [B,21]
                const float* __restrict__ W1,   // [100,21]
                const float* __restrict__ b1,   // [100]
                const float* __restrict__ W2,   // [10,100]
                const float* __restrict__ b2,   // [10]
                float* __restrict__ out,        // [2,25,B,10]
                int B)
{
    // 48B rows (6 x u64), 16B-aligned: row j holds W2^T[j] as 5 packed f32x2 + pad
    __shared__ __align__(16) unsigned long long sW2p[N1][6];   // 4.8KB
    __shared__ float2 sc2[N1 / 2][BDIM];                       // cur1 pairs, 25.6KB

    const int tid = threadIdx.x;

    for (int i = tid; i < N1 * 5; i += BDIM) {
        int j = i / 5, k2 = i % 5;
        float lo = W2[(2 * k2) * N1 + j];
        float hi = W2[(2 * k2 + 1) * N1 + j];
        unsigned long long p;
        asm("mov.b64 %0, {%1, %2};" : "=l"(p) : "f"(lo), "f"(hi));
        sW2p[j][k2] = p;
    }
    __syncthreads();

    const int e = blockIdx.x * BDIM + tid;
    if (e >= B) return;

    // ---- prologue: cur1 = ascending-k fma chain from 0, then +b1 ----
    // W1/b1 read straight from global (uniform broadcast, L1-served, one-time)
    {
        float xv[KIN];
#pragma unroll
        for (int k = 0; k < KIN; k++) xv[k] = __ldg(&x[e * KIN + k]);
#pragma unroll 2
        for (int j2 = 0; j2 < N1 / 2; j2++) {
            float a0 = 0.0f, a1 = 0.0f;
            const float* w0r = &W1[(2 * j2) * KIN];
            const float* w1r = &W1[(2 * j2 + 1) * KIN];
#pragma unroll
            for (int k = 0; k < KIN; k++) {
                a0 = fmaf(xv[k], __ldg(&w0r[k]), a0);
                a1 = fmaf(xv[k], __ldg(&w1r[k]), a1);
            }
            sc2[j2][tid] = make_float2(__fadd_rn(a0, __ldg(&b1[2 * j2])),
                                       __fadd_rn(a1, __ldg(&b1[2 * j2 + 1])));
        }
    }

    // b2 in registers
    float rb2[N2];
#pragma unroll
    for (int k = 0; k < N2; k++) rb2[k] = __ldg(&b2[k]);

    float mem[N1];
#pragma unroll
    for (int j = 0; j < N1; j++) mem[j] = 0.0f;

    float mem2[N2];
#pragma unroll
    for (int k = 0; k < N2; k++) mem2[k] = 0.0f;

    float* __restrict__ spkout = out;
    float* __restrict__ memout = out + (size_t)NSTEPS * B * N2;

    for (int t = 0; t < NSTEPS; t++) {
        unsigned long long acc2[5];
#pragma unroll
        for (int k = 0; k < 5; k++) acc2[k] = 0ull;

        // ---- layer 1: two neurons per iteration; vectorized W2 row loads ----
#pragma unroll 5
        for (int j2 = 0; j2 < N1 / 2; j2++) {
            const float2 c2 = sc2[j2][tid];

            // neuron j = 2*j2
            {
                const int j = 2 * j2;
                float mprev = mem[j];
                float r = (mprev > TH) ? 1.0f : 0.0f;
                float m = __fsub_rn(fmaf(BETA, mprev, c2.x), r);
                mem[j] = m;
                float s = (m > TH) ? 1.0f : 0.0f;
                unsigned long long ss;
                PACK_SS(ss, s);
                const ulonglong2 w01 = *reinterpret_cast<const ulonglong2*>(&sW2p[j][0]);
                const ulonglong2 w23 = *reinterpret_cast<const ulonglong2*>(&sW2p[j][2]);
                const unsigned long long w4 = sW2p[j][4];
                FMA_F32X2(acc2[0], ss, w01.x, acc2[0]);
                FMA_F32X2(acc2[1], ss, w01.y, acc2[1]);
                FMA_F32X2(acc2[2], ss, w23.x, acc2[2]);
                FMA_F32X2(acc2[3], ss, w23.y, acc2[3]);
                FMA_F32X2(acc2[4], ss, w4,    acc2[4]);
            }
            // neuron j = 2*j2 + 1
            {
                const int j = 2 * j2 + 1;
                float mprev = mem[j];
                float r = (mprev > TH) ? 1.0f : 0.0f;
                float m = __fsub_rn(fmaf(BETA, mprev, c2.y), r);
                mem[j] = m;
                float s = (m > TH) ? 1.0f : 0.0f;
                unsigned long long ss;
                PACK_SS(ss, s);
                const ulonglong2 w01 = *reinterpret_cast<const ulonglong2*>(&sW2p[j][0]);
                const ulonglong2 w23 = *reinterpret_cast<const ulonglong2*>(&sW2p[j][2]);
                const unsigned long long w4 = sW2p[j][4];
                FMA_F32X2(acc2[0], ss, w01.x, acc2[0]);
                FMA_F32X2(acc2[1], ss, w01.y, acc2[1]);
                FMA_F32X2(acc2[2], ss, w23.x, acc2[2]);
                FMA_F32X2(acc2[3], ss, w23.y, acc2[3]);
                FMA_F32X2(acc2[4], ss, w4,    acc2[4]);
            }
        }

        // ---- layer 2 (scalar, 10 neurons) ----
        const size_t obase = ((size_t)t * B + e) * N2;
        float so[N2], mo[N2];
#pragma unroll
        for (int k = 0; k < 5; k++) {
            float a0, a1;
            UNPACK_F32X2(a0, a1, acc2[k]);
#pragma unroll
            for (int q = 0; q < 2; q++) {
                int kk = 2 * k + q;
                float av = q ? a1 : a0;
                float cc = __fadd_rn(av, rb2[kk]);      // bias after full sum
                float mprev = mem2[kk];
                float r = (mprev > TH) ? 1.0f : 0.0f;
                float m = __fsub_rn(fmaf(BETA, mprev, cc), r);
                mem2[kk] = m;
                so[kk] = (m > TH) ? 1.0f : 0.0f;
                mo[kk] = m;
            }
        }
#pragma unroll
        for (int k = 0; k < N2; k += 2) {
            *(float2*)&spkout[obase + k] = make_float2(so[k], so[k + 1]);
            *(float2*)&memout[obase + k] = make_float2(mo[k], mo[k + 1]);
        }
    }
}

extern "C" void kernel_launch(void* const* d_in, const int* in_sizes, int n_in,
                              void* d_out, int out_size)
{
    const float* x  = (const float*)d_in[0];
    const float* W1 = (const float*)d_in[1];
    const float* b1 = (const float*)d_in[2];
    const float* W2 = (const float*)d_in[3];
    const float* b2 = (const float*)d_in[4];
    float* out = (float*)d_out;

    const int B = in_sizes[0] / KIN;
    const int grid = (B + BDIM - 1) / BDIM;
    snn_kernel<<<grid, BDIM>>>(x, W1, b1, W2, b2, out, B);
}